// round 5
// baseline (speedup 1.0000x reference)
#include <cuda_runtime.h>
#include <cuda_fp16.h>

#define A_DIM 256
#define H_DIM 512
#define S_DIM 1024
#define T_DIM 256
#define B_DIM 4
#define MS (B_DIM * S_DIM)   /* 4096 rows of eh */
#define MT (B_DIM * T_DIM)   /* 1024 rows of dh */

__device__ float g_ehT[A_DIM * MS];   // [A][B*S]
__device__ float g_dh[MT * A_DIM];    // [B*T][A]

// ---- packed helpers ----
__device__ __forceinline__ void ffma2(float2& d, const float2 a, const float2 b) {
    unsigned long long ud = *(const unsigned long long*)&d;
    unsigned long long ua = *(const unsigned long long*)&a;
    unsigned long long ub = *(const unsigned long long*)&b;
    asm("fma.rn.f32x2 %0, %1, %2, %0;" : "+l"(ud) : "l"(ua), "l"(ub));
    *(unsigned long long*)&d = ud;
}
__device__ __forceinline__ float2 fadd2(const float2 a, const float2 b) {
    unsigned long long ua = *(const unsigned long long*)&a;
    unsigned long long ub = *(const unsigned long long*)&b;
    unsigned long long uo;
    asm("add.rn.f32x2 %0, %1, %2;" : "=l"(uo) : "l"(ua), "l"(ub));
    return *(float2*)&uo;
}
__device__ __forceinline__ __half2 tanh2(__half2 x) {
    unsigned u = *(unsigned*)&x;
    asm("tanh.approx.f16x2 %0, %1;" : "=r"(u) : "r"(u));
    return *(__half2*)&u;
}

// ============================================================================
// Dual GEMM, 8x8 per-thread tile, double-buffered.
//   blockIdx.x <  128 : ehT = (enc @ Wh + bh)^T   (M=4096, 32x4 tiles)
//   blockIdx.x >= 128 : dh  =  dec @ Ws + bs      (M=1024,  8x4 tiles)
// BM=128, BN=64, BK=16, 128 threads.
// ============================================================================
#define GBK 16
#define GNSTEP (H_DIM / GBK)
__global__ __launch_bounds__(128) void dual_gemm_kernel(
    const float* __restrict__ enc, const float* __restrict__ dec,
    const float* __restrict__ Wh,  const float* __restrict__ bh,
    const float* __restrict__ Wsm, const float* __restrict__ bsm,
    float* __restrict__ ehT, float* __restrict__ dh)
{
    __shared__ float Xs[2][GBK][128];
    __shared__ float Wt[2][GBK][64];

    bool p2 = blockIdx.x >= 128;
    const float* X    = p2 ? dec : enc;
    const float* W    = p2 ? Wsm : Wh;
    const float* bias = p2 ? bsm : bh;
    int bx = p2 ? (blockIdx.x - 128) : blockIdx.x;
    int m0 = (bx >> 2) * 128;
    int n0 = (bx & 3) * 64;
    const int K = H_DIM, N = A_DIM;

    int tid  = threadIdx.x;
    int trow = (tid >> 3) * 8;   // 0..120
    int tcol = (tid & 7) * 8;    // 0..56

    // loader mapping: X row = tid (full 16-k row per thread); W: 2 float4
    const float* xrow = &X[(size_t)(m0 + tid) * K];
    int wk = tid >> 3;           // 0..15
    int wn = (tid & 7) * 8;      // 0..56

    float2 acc[4][8];            // [row-pair][col]
#pragma unroll
    for (int p = 0; p < 4; p++)
#pragma unroll
        for (int j = 0; j < 8; j++) acc[p][j] = make_float2(0.f, 0.f);

    float4 rx0, rx1, rx2, rx3, rw0, rw1;

    // prologue: fetch step 0
    rx0 = *(const float4*)&xrow[0];
    rx1 = *(const float4*)&xrow[4];
    rx2 = *(const float4*)&xrow[8];
    rx3 = *(const float4*)&xrow[12];
    rw0 = *(const float4*)&W[(size_t)(wk) * N + n0 + wn];
    rw1 = *(const float4*)&W[(size_t)(wk) * N + n0 + wn + 4];
    {
        float xv[16] = {rx0.x,rx0.y,rx0.z,rx0.w, rx1.x,rx1.y,rx1.z,rx1.w,
                        rx2.x,rx2.y,rx2.z,rx2.w, rx3.x,rx3.y,rx3.z,rx3.w};
#pragma unroll
        for (int k = 0; k < 16; k++) Xs[0][k][tid] = xv[k];
        *(float4*)&Wt[0][wk][wn]     = rw0;
        *(float4*)&Wt[0][wk][wn + 4] = rw1;
    }
    __syncthreads();

    for (int step = 0; step < GNSTEP; step++) {
        int cur = step & 1;
        if (step + 1 < GNSTEP) {
            int k0 = (step + 1) * GBK;
            rx0 = *(const float4*)&xrow[k0];
            rx1 = *(const float4*)&xrow[k0 + 4];
            rx2 = *(const float4*)&xrow[k0 + 8];
            rx3 = *(const float4*)&xrow[k0 + 12];
            rw0 = *(const float4*)&W[(size_t)(k0 + wk) * N + n0 + wn];
            rw1 = *(const float4*)&W[(size_t)(k0 + wk) * N + n0 + wn + 4];
        }

#pragma unroll
        for (int kk = 0; kk < GBK; kk++) {
            float4 a0 = *(const float4*)&Xs[cur][kk][trow];
            float4 a1 = *(const float4*)&Xs[cur][kk][trow + 4];
            float4 b0 = *(const float4*)&Wt[cur][kk][tcol];
            float4 b1 = *(const float4*)&Wt[cur][kk][tcol + 4];
            float2 ap[4] = { make_float2(a0.x, a0.y), make_float2(a0.z, a0.w),
                             make_float2(a1.x, a1.y), make_float2(a1.z, a1.w) };
            float bs8[8] = {b0.x, b0.y, b0.z, b0.w, b1.x, b1.y, b1.z, b1.w};
#pragma unroll
            for (int j = 0; j < 8; j++) {
                float2 bd = make_float2(bs8[j], bs8[j]);
                ffma2(acc[0][j], ap[0], bd);
                ffma2(acc[1][j], ap[1], bd);
                ffma2(acc[2][j], ap[2], bd);
                ffma2(acc[3][j], ap[3], bd);
            }
        }

        if (step + 1 < GNSTEP) {
            int nxt = cur ^ 1;
            float xv[16] = {rx0.x,rx0.y,rx0.z,rx0.w, rx1.x,rx1.y,rx1.z,rx1.w,
                            rx2.x,rx2.y,rx2.z,rx2.w, rx3.x,rx3.y,rx3.z,rx3.w};
#pragma unroll
            for (int k = 0; k < 16; k++) Xs[nxt][k][tid] = xv[k];
            *(float4*)&Wt[nxt][wk][wn]     = rw0;
            *(float4*)&Wt[nxt][wk][wn + 4] = rw1;
        }
        __syncthreads();
    }

    float bj[8];
#pragma unroll
    for (int j = 0; j < 8; j++) bj[j] = bias[n0 + tcol + j];

    if (!p2) {
        // transposed store: ehT[n][m], m = m0+trow..+7 contiguous
#pragma unroll
        for (int j = 0; j < 8; j++) {
            size_t base = (size_t)(n0 + tcol + j) * MS + m0 + trow;
            float4 v0 = make_float4(acc[0][j].x + bj[j], acc[0][j].y + bj[j],
                                    acc[1][j].x + bj[j], acc[1][j].y + bj[j]);
            float4 v1 = make_float4(acc[2][j].x + bj[j], acc[2][j].y + bj[j],
                                    acc[3][j].x + bj[j], acc[3][j].y + bj[j]);
            *(float4*)&ehT[base]     = v0;
            *(float4*)&ehT[base + 4] = v1;
        }
    } else {
#pragma unroll
        for (int p = 0; p < 4; p++) {
            float4 e0 = make_float4(acc[p][0].x + bj[0], acc[p][1].x + bj[1],
                                    acc[p][2].x + bj[2], acc[p][3].x + bj[3]);
            float4 e1 = make_float4(acc[p][4].x + bj[4], acc[p][5].x + bj[5],
                                    acc[p][6].x + bj[6], acc[p][7].x + bj[7]);
            float4 o0 = make_float4(acc[p][0].y + bj[0], acc[p][1].y + bj[1],
                                    acc[p][2].y + bj[2], acc[p][3].y + bj[3]);
            float4 o1 = make_float4(acc[p][4].y + bj[4], acc[p][5].y + bj[5],
                                    acc[p][6].y + bj[6], acc[p][7].y + bj[7]);
            size_t re = (size_t)(m0 + trow + 2*p)     * A_DIM + n0 + tcol;
            size_t ro = (size_t)(m0 + trow + 2*p + 1) * A_DIM + n0 + tcol;
            *(float4*)&dh[re] = e0; *(float4*)&dh[re + 4] = e1;
            *(float4*)&dh[ro] = o0; *(float4*)&dh[ro + 4] = o1;
        }
    }
}

// ============================================================================
// Persistent attn+softmax, f16x2 tanh (2 tanh per MUFU op), f32 accumulation.
// 148 CTAs = 4 x 37; 1024 threads (thread = one s); 7|6 t padded to 8 slots.
// ============================================================================
#define CTAS_PER_B 37
__global__ __launch_bounds__(1024, 1) void attn_softmax_kernel(
    const float* __restrict__ Wv, float* __restrict__ out)
{
    __shared__ float sdh[A_DIM][8];
    __shared__ float swv[A_DIM];
    __shared__ float redm[32 * 8];
    __shared__ float bmax[8];
    __shared__ float bsum[8];

    int b   = blockIdx.x / CTAS_PER_B;
    int idx = blockIdx.x % CTAS_PER_B;
    int t0, nt;
    if (idx < 34) { t0 = idx * 7;              nt = 7; }
    else          { t0 = 238 + (idx - 34) * 6; nt = 6; }

    int tid = threadIdx.x;
    for (int i = tid; i < A_DIM * 8; i += 1024) {
        int a = i >> 3, t = i & 7;
        int tt = t < nt ? t : nt - 1;
        sdh[a][t] = g_dh[(size_t)(b * T_DIM + t0 + tt) * A_DIM + a];
    }
    if (tid < A_DIM) swv[tid] = Wv[tid];
    __syncthreads();

    int w = tid >> 5, l = tid & 31;
    const float* ehp = &g_ehT[(size_t)b * S_DIM + tid];

    float acc[8];
#pragma unroll
    for (int t = 0; t < 8; t++) acc[t] = 0.f;

#pragma unroll 4
    for (int a = 0; a < A_DIM; a++) {
        float e  = __ldg(ehp + (size_t)a * MS);
        float wv = swv[a];
        float4 d0 = *(const float4*)&sdh[a][0];
        float4 d1 = *(const float4*)&sdh[a][4];
        float2 e2 = make_float2(e, e);

        float2 x0 = fadd2(e2, make_float2(d0.x, d0.y));
        float2 x1 = fadd2(e2, make_float2(d0.z, d0.w));
        float2 x2 = fadd2(e2, make_float2(d1.x, d1.y));
        float2 x3 = fadd2(e2, make_float2(d1.z, d1.w));

        float2 r0 = __half22float2(tanh2(__floats2half2_rn(x0.x, x0.y)));
        float2 r1 = __half22float2(tanh2(__floats2half2_rn(x1.x, x1.y)));
        float2 r2 = __half22float2(tanh2(__floats2half2_rn(x2.x, x2.y)));
        float2 r3 = __half22float2(tanh2(__floats2half2_rn(x3.x, x3.y)));

        acc[0] = fmaf(wv, r0.x, acc[0]); acc[1] = fmaf(wv, r0.y, acc[1]);
        acc[2] = fmaf(wv, r1.x, acc[2]); acc[3] = fmaf(wv, r1.y, acc[3]);
        acc[4] = fmaf(wv, r2.x, acc[4]); acc[5] = fmaf(wv, r2.y, acc[5]);
        acc[6] = fmaf(wv, r3.x, acc[6]); acc[7] = fmaf(wv, r3.y, acc[7]);
    }

    // ---- per-t block max
#pragma unroll
    for (int t = 0; t < 8; t++) {
        float m = acc[t];
#pragma unroll
        for (int o = 16; o > 0; o >>= 1) m = fmaxf(m, __shfl_xor_sync(0xffffffffu, m, o));
        if (l == 0) redm[w * 8 + t] = m;
    }
    __syncthreads();
    if (w < 8) {
        float m = redm[l * 8 + w];
#pragma unroll
        for (int o = 16; o > 0; o >>= 1) m = fmaxf(m, __shfl_xor_sync(0xffffffffu, m, o));
        if (l == 0) bmax[w] = m;
    }
    __syncthreads();

    // ---- exp + per-t block sum
    float ex[8];
#pragma unroll
    for (int t = 0; t < 8; t++) {
        ex[t] = __expf(acc[t] - bmax[t]);
        float s = ex[t];
#pragma unroll
        for (int o = 16; o > 0; o >>= 1) s += __shfl_xor_sync(0xffffffffu, s, o);
        if (l == 0) redm[w * 8 + t] = s;
    }
    __syncthreads();
    if (w < 8) {
        float s = redm[l * 8 + w];
#pragma unroll
        for (int o = 16; o > 0; o >>= 1) s += __shfl_xor_sync(0xffffffffu, s, o);
        if (l == 0) bsum[w] = s;
    }
    __syncthreads();

#pragma unroll
    for (int t = 0; t < 8; t++) {
        if (t < nt)
            out[(size_t)(b * T_DIM + t0 + t) * S_DIM + tid] = ex[t] * (1.f / bsum[t]);
    }
}

extern "C" void kernel_launch(void* const* d_in, const int* in_sizes, int n_in,
                              void* d_out, int out_size)
{
    const float* enc = (const float*)d_in[0];  // [4,1024,512]
    const float* dec = (const float*)d_in[1];  // [4,256,512]
    const float* Wh  = (const float*)d_in[2];  // [512,256]
    const float* bh  = (const float*)d_in[3];  // [256]
    const float* Ws  = (const float*)d_in[4];  // [512,256]
    const float* bs  = (const float*)d_in[5];  // [256]
    const float* Wv  = (const float*)d_in[6];  // [256,1]
    // d_in[7] = bv: softmax-invariant shift, unused.
    float* out = (float*)d_out;                // [4,256,1024]

    float* ehT;
    float* dh;
    cudaGetSymbolAddress((void**)&ehT, g_ehT);
    cudaGetSymbolAddress((void**)&dh, g_dh);

    // 128 eh-tiles + 32 dec-tiles = 160 CTAs
    dual_gemm_kernel<<<160, 128>>>(enc, dec, Wh, bh, Ws, bs, ehT, dh);

    attn_softmax_kernel<<<B_DIM * CTAS_PER_B, 1024>>>(Wv, out);   // 148 CTAs
}

// round 6
// speedup vs baseline: 1.2419x; 1.2419x over previous
#include <cuda_runtime.h>

#define A_DIM 256
#define H_DIM 512
#define S_DIM 1024
#define T_DIM 256
#define B_DIM 4
#define MS (B_DIM * S_DIM)   /* 4096 rows of eh */
#define MT (B_DIM * T_DIM)   /* 1024 rows of dh */

__device__ float g_ehT[A_DIM * MS];   // [A][B*S]
__device__ float g_dh[MT * A_DIM];    // [B*T][A]

__device__ __forceinline__ float tanh_fast(float x) {
    float y;
    asm("tanh.approx.f32 %0, %1;" : "=f"(y) : "f"(x));
    return y;
}
__device__ __forceinline__ void ffma2(float2& d, const float2 a, const float2 b) {
    unsigned long long ud = *(const unsigned long long*)&d;
    unsigned long long ua = *(const unsigned long long*)&a;
    unsigned long long ub = *(const unsigned long long*)&b;
    asm("fma.rn.f32x2 %0, %1, %2, %0;" : "+l"(ud) : "l"(ua), "l"(ub));
    *(unsigned long long*)&d = ud;
}

// ============================================================================
// Dual GEMM: 64x64 tiles, 256 threads, 4x4 per thread (2 row-pairs x 4 cols
// via fma.rn.f32x2). 320 CTAs -> 4.3 warps/SMSP (latency actually hidden).
//   blockIdx.x <  64 : ehT = (enc @ Wh + bh)^T   (M=4096)
//   blockIdx.x >= 64 : dh  =  dec @ Ws + bs      (M=1024)
// ============================================================================
#define GBK 16
__global__ __launch_bounds__(256) void dual_gemm_kernel(
    const float* __restrict__ enc, const float* __restrict__ dec,
    const float* __restrict__ Wh,  const float* __restrict__ bh,
    const float* __restrict__ Wsm, const float* __restrict__ bsm,
    float* __restrict__ ehT, float* __restrict__ dh)
{
    __shared__ float Xs[GBK][68];   // pad 68: keeps float4 reads aligned
    __shared__ float Wt[GBK][64];

    bool p2 = blockIdx.x >= 64;
    const float* X    = p2 ? dec : enc;
    const float* W    = p2 ? Wsm : Wh;
    const float* bias = p2 ? bsm : bh;
    int m0 = (p2 ? (blockIdx.x - 64) : blockIdx.x) * 64;
    int n0 = blockIdx.y * 64;
    const int K = H_DIM, N = A_DIM;

    int tid  = threadIdx.x;
    int trow = (tid >> 4) * 4;   // 0..60
    int tcol = (tid & 15) * 4;   // 0..60

    // loader mapping (256 threads, one float4 each per tile)
    int lm = tid >> 2;           // 0..63  (X row)
    int lk = (tid & 3) * 4;      // 0,4,8,12
    int wk = tid >> 4;           // 0..15  (W row)
    int wn = (tid & 15) * 4;     // 0..60

    float2 acc[2][4];            // [row-pair][col]
#pragma unroll
    for (int p = 0; p < 2; p++)
#pragma unroll
        for (int j = 0; j < 4; j++) acc[p][j] = make_float2(0.f, 0.f);

    for (int k0 = 0; k0 < K; k0 += GBK) {
        float4 xv = *(const float4*)&X[(size_t)(m0 + lm) * K + k0 + lk];
        Xs[lk + 0][lm] = xv.x;
        Xs[lk + 1][lm] = xv.y;
        Xs[lk + 2][lm] = xv.z;
        Xs[lk + 3][lm] = xv.w;
        *(float4*)&Wt[wk][wn] = *(const float4*)&W[(size_t)(k0 + wk) * N + n0 + wn];
        __syncthreads();

#pragma unroll
        for (int kk = 0; kk < GBK; kk++) {
            float4 e4 = *(const float4*)&Xs[kk][trow];   // warp-broadcast
            float4 w4 = *(const float4*)&Wt[kk][tcol];
            float2 ep0 = make_float2(e4.x, e4.y);
            float2 ep1 = make_float2(e4.z, e4.w);
            float ws[4] = {w4.x, w4.y, w4.z, w4.w};
#pragma unroll
            for (int j = 0; j < 4; j++) {
                float2 wd = make_float2(ws[j], ws[j]);
                ffma2(acc[0][j], ep0, wd);
                ffma2(acc[1][j], ep1, wd);
            }
        }
        __syncthreads();
    }

    float bj[4];
#pragma unroll
    for (int j = 0; j < 4; j++) bj[j] = bias[n0 + tcol + j];

    if (!p2) {
        // transposed store: ehT[n][m], rows trow..trow+3 contiguous
#pragma unroll
        for (int j = 0; j < 4; j++) {
            size_t base = (size_t)(n0 + tcol + j) * MS + m0 + trow;
            float4 v = make_float4(acc[0][j].x + bj[j], acc[0][j].y + bj[j],
                                   acc[1][j].x + bj[j], acc[1][j].y + bj[j]);
            *(float4*)&ehT[base] = v;
        }
    } else {
#pragma unroll
        for (int p = 0; p < 2; p++) {
            float4 ve = make_float4(acc[p][0].x + bj[0], acc[p][1].x + bj[1],
                                    acc[p][2].x + bj[2], acc[p][3].x + bj[3]);
            float4 vo = make_float4(acc[p][0].y + bj[0], acc[p][1].y + bj[1],
                                    acc[p][2].y + bj[2], acc[p][3].y + bj[3]);
            *(float4*)&dh[(size_t)(m0 + trow + 2*p)     * A_DIM + n0 + tcol] = ve;
            *(float4*)&dh[(size_t)(m0 + trow + 2*p + 1) * A_DIM + n0 + tcol] = vo;
        }
    }
}

// ============================================================================
// Persistent attn+softmax (round-3 proven version, f32 tanh).
// 148 CTAs = 4 x 37; 1024 threads (thread = one s); 7|6 t padded to 8 slots.
// bv dropped (softmax-invariant).
// ============================================================================
#define CTAS_PER_B 37
#define NT_MAX 7
__global__ __launch_bounds__(1024, 1) void attn_softmax_kernel(
    const float* __restrict__ Wv, float* __restrict__ out)
{
    __shared__ float sdh[A_DIM][8];
    __shared__ float swv[A_DIM];
    __shared__ float redm[32 * 8];
    __shared__ float bmax[8];
    __shared__ float bsum[8];

    int b   = blockIdx.x / CTAS_PER_B;
    int idx = blockIdx.x % CTAS_PER_B;
    int t0, nt;
    if (idx < 34) { t0 = idx * 7;              nt = 7; }
    else          { t0 = 238 + (idx - 34) * 6; nt = 6; }

    int tid = threadIdx.x;
    for (int i = tid; i < A_DIM * 8; i += 1024) {
        int a = i >> 3, t = i & 7;
        int tt = t < nt ? t : nt - 1;
        sdh[a][t] = g_dh[(size_t)(b * T_DIM + t0 + tt) * A_DIM + a];
    }
    if (tid < A_DIM) swv[tid] = Wv[tid];
    __syncthreads();

    int w = tid >> 5, l = tid & 31;
    const float* ehp = &g_ehT[(size_t)b * S_DIM + tid];

    float acc[NT_MAX];
#pragma unroll
    for (int t = 0; t < NT_MAX; t++) acc[t] = 0.f;

#pragma unroll 4
    for (int a = 0; a < A_DIM; a++) {
        float e  = __ldg(ehp + (size_t)a * MS);
        float wv = swv[a];
        float4 d0 = *(const float4*)&sdh[a][0];
        float4 d1 = *(const float4*)&sdh[a][4];
        acc[0] += wv * tanh_fast(e + d0.x);
        acc[1] += wv * tanh_fast(e + d0.y);
        acc[2] += wv * tanh_fast(e + d0.z);
        acc[3] += wv * tanh_fast(e + d0.w);
        acc[4] += wv * tanh_fast(e + d1.x);
        acc[5] += wv * tanh_fast(e + d1.y);
        acc[6] += wv * tanh_fast(e + d1.z);
    }

    // ---- per-t block max
#pragma unroll
    for (int t = 0; t < NT_MAX; t++) {
        float m = acc[t];
#pragma unroll
        for (int o = 16; o > 0; o >>= 1) m = fmaxf(m, __shfl_xor_sync(0xffffffffu, m, o));
        if (l == 0) redm[w * 8 + t] = m;
    }
    __syncthreads();
    if (w < NT_MAX) {
        float m = redm[l * 8 + w];
#pragma unroll
        for (int o = 16; o > 0; o >>= 1) m = fmaxf(m, __shfl_xor_sync(0xffffffffu, m, o));
        if (l == 0) bmax[w] = m;
    }
    __syncthreads();

    // ---- exp + per-t block sum
    float ex[NT_MAX];
#pragma unroll
    for (int t = 0; t < NT_MAX; t++) {
        ex[t] = __expf(acc[t] - bmax[t]);
        float s = ex[t];
#pragma unroll
        for (int o = 16; o > 0; o >>= 1) s += __shfl_xor_sync(0xffffffffu, s, o);
        if (l == 0) redm[w * 8 + t] = s;
    }
    __syncthreads();
    if (w < NT_MAX) {
        float s = redm[l * 8 + w];
#pragma unroll
        for (int o = 16; o > 0; o >>= 1) s += __shfl_xor_sync(0xffffffffu, s, o);
        if (l == 0) bsum[w] = s;
    }
    __syncthreads();

#pragma unroll
    for (int t = 0; t < NT_MAX; t++) {
        if (t < nt)
            out[(size_t)(b * T_DIM + t0 + t) * S_DIM + tid] = ex[t] * (1.f / bsum[t]);
    }
}

extern "C" void kernel_launch(void* const* d_in, const int* in_sizes, int n_in,
                              void* d_out, int out_size)
{
    const float* enc = (const float*)d_in[0];  // [4,1024,512]
    const float* dec = (const float*)d_in[1];  // [4,256,512]
    const float* Wh  = (const float*)d_in[2];  // [512,256]
    const float* bh  = (const float*)d_in[3];  // [256]
    const float* Ws  = (const float*)d_in[4];  // [512,256]
    const float* bs  = (const float*)d_in[5];  // [256]
    const float* Wv  = (const float*)d_in[6];  // [256,1]
    // d_in[7] = bv: softmax-invariant shift, unused.
    float* out = (float*)d_out;                // [4,256,1024]

    float* ehT;
    float* dh;
    cudaGetSymbolAddress((void**)&ehT, g_ehT);
    cudaGetSymbolAddress((void**)&dh, g_dh);

    dim3 g1(64 + 16, A_DIM / 64);              // 320 CTAs, both GEMMs
    dual_gemm_kernel<<<g1, 256>>>(enc, dec, Wh, bh, Ws, bs, ehT, dh);

    attn_softmax_kernel<<<B_DIM * CTAS_PER_B, 1024>>>(Wv, out);   // 148 CTAs
}